// round 16
// baseline (speedup 1.0000x reference)
#include <cuda_runtime.h>
#include <cuda_fp16.h>
#include <math.h>
#include <stdint.h>

#define BATCH 2
#define SEQ   1024
#define EDIM  1024
#define HEADS 16
#define HDIM  64
#define MFEAT 128
#define BH    (BATCH*HEADS)     /* 32 */
#define CHUNK 64
#define NCHUNK (SEQ/CHUNK)      /* 16 */

// ---------------- scratch (device globals: no allocation allowed) ----------
__device__ float d_q[BATCH*SEQ*EDIM];
__device__ float d_k[BATCH*SEQ*EDIM];
__device__ float d_v[BATCH*SEQ*EDIM];
__device__ float d_phik[BH*SEQ*MFEAT];           // raw log-phik (phi -> stepA)
__device__ float d_Ssum[BH*NCHUNK*MFEAT*HDIM];
__device__ float d_ssum[BH*NCHUNK*MFEAT];
__device__ float d_spre[BH*NCHUNK*MFEAT];
__device__ unsigned d_gmax;

// fp16 scratch
__device__ __half d_x16[BATCH*SEQ*EDIM];         // x16 for QKV, then v16
__device__ __half d_wq16[EDIM*EDIM], d_wk16[EDIM*EDIM];
__device__ __half d_wv16[EDIM*EDIM], d_wo16[EDIM*EDIM];
__device__ __half d_at16[BATCH*SEQ*EDIM];
__device__ __half d_phiq16[BH*SEQ*MFEAT];
__device__ __half d_phik16[BH*SEQ*MFEAT];
__device__ __half d_kvp16[BH*NCHUNK*MFEAT*HDIM];

// ordered-float <-> uint monotone mapping for atomicMax on floats
__device__ __forceinline__ unsigned enc_f(float f) {
    unsigned u = __float_as_uint(f);
    return (u & 0x80000000u) ? ~u : (u | 0x80000000u);
}
__device__ __forceinline__ float dec_f(unsigned u) {
    return (u & 0x80000000u) ? __uint_as_float(u ^ 0x80000000u)
                             : __uint_as_float(~u);
}

__global__ void reset_kernel() { d_gmax = 0x007FFFFFu; /* enc(-inf) */ }

// ============================ mma.sync helpers ==============================
__device__ __forceinline__ uint32_t smem_u32(const void* p) {
    uint32_t a;
    asm("{ .reg .u64 t; cvta.to.shared.u64 t, %1; cvt.u32.u64 %0, t; }"
        : "=r"(a) : "l"(p));
    return a;
}

#define LDSM4(r, a) \
    asm volatile("ldmatrix.sync.aligned.m8n8.x4.shared.b16 {%0,%1,%2,%3}, [%4];" \
        : "=r"((r)[0]), "=r"((r)[1]), "=r"((r)[2]), "=r"((r)[3]) : "r"(a))

#define MMAH16816(d, a, b0, b1) \
    asm volatile("mma.sync.aligned.m16n8k16.row.col.f32.f16.f16.f32 " \
        "{%0,%1,%2,%3}, {%4,%5,%6,%7}, {%8,%9}, {%0,%1,%2,%3};" \
        : "+f"((d)[0]), "+f"((d)[1]), "+f"((d)[2]), "+f"((d)[3]) \
        : "r"((a)[0]), "r"((a)[1]), "r"((a)[2]), "r"((a)[3]), \
          "r"(b0), "r"(b1))

__device__ __forceinline__ void cp16(uint32_t d, const void* s) {
    asm volatile("cp.async.cg.shared.global [%0], [%1], 16;" :: "r"(d), "l"(s));
}
#define CP_COMMIT() asm volatile("cp.async.commit_group;" ::: "memory")
#define CP_WAIT1()  asm volatile("cp.async.wait_group 1;" ::: "memory")
#define CP_WAIT0()  asm volatile("cp.async.wait_group 0;" ::: "memory")

// ------- pre-pass: x -> fp16 -------------------------------------------------
__global__ void __launch_bounds__(256) cvt_x_kernel(
    const float* __restrict__ x, __half* __restrict__ x16)
{
    size_t i = (size_t)blockIdx.x * 256 + threadIdx.x;
    float4 v = *((const float4*)x + i);
    __half2 a = __floats2half2_rn(v.x, v.y);
    __half2 b = __floats2half2_rn(v.z, v.w);
    uint2 u; u.x = *(uint32_t*)&a; u.y = *(uint32_t*)&b;
    *(uint2*)(x16 + i * 4) = u;
}

// ------- pre-pass: 4 weights -> fp16; Wq/Wk pre-scaled by 64^-0.25 ----------
__global__ void __launch_bounds__(256) cvt_w4_kernel(
    const float* __restrict__ s0, const float* __restrict__ s1,
    const float* __restrict__ s2, const float* __restrict__ s3,
    __half* __restrict__ w0, __half* __restrict__ w1,
    __half* __restrict__ w2, __half* __restrict__ w3)
{
    const float* src = s0; __half* w = w0;
    float sc = 0.35355339059327373f;                 // Wq scaled
    if (blockIdx.y == 1) { src = s1; w = w1; }       // Wk scaled
    if (blockIdx.y == 2) { src = s2; w = w2; sc = 1.f; }
    if (blockIdx.y == 3) { src = s3; w = w3; sc = 1.f; }
    size_t i = (size_t)blockIdx.x * 256 + threadIdx.x;
    float4 v = *((const float4*)src + i);
    __half2 a = __floats2half2_rn(v.x * sc, v.y * sc);
    __half2 b = __floats2half2_rn(v.z * sc, v.w * sc);
    uint2 u; u.x = *(uint32_t*)&a; u.y = *(uint32_t*)&b;
    *(uint2*)(w + i * 4) = u;
}

// ====== fp16 1-term GEMM: C = A @ B^T (+bias), both single fp16 =============
// CTA tile 128x128, K-chunk 64 (144B rows, conflict-free ldmatrix), 3-stage
// cp.async, 2 CTAs/SM, one barrier per chunk, ks-loop fragment double-buffer.
#define PARTK 9216                           /* 128*72 elems per part */
#define STGK_BYTES (2 * PARTK * 2)           /* A+B parts = 36864 B */

__global__ void __launch_bounds__(256, 2) mma_gemm_h(
    const __half* __restrict__ A,
    const __half* __restrict__ B0, const __half* __restrict__ B1,
    const __half* __restrict__ B2,
    float* __restrict__ C0, float* __restrict__ C1, float* __restrict__ C2,
    const float* __restrict__ bias, int N, int K)
{
    extern __shared__ __half smh[];
    const __half* B = B0; float* C = C0;
    if (blockIdx.z == 1) { B = B1; C = C1; }
    if (blockIdx.z == 2) { B = B2; C = C2; }

    const int tid = threadIdx.x, wid = tid >> 5, lane = tid & 31;
    const int wy = wid & 3, wx = wid >> 2;          // warp grid 4(M) x 2(N)
    const int row0 = blockIdx.y * 128, col0 = blockIdx.x * 128;
    const uint32_t sb = smem_u32(smh);

    const int a_rl = lane & 15, a_ko = (lane >> 4) * 8;
    const int b_nl = (lane & 7) + (lane >> 4) * 8, b_ko = ((lane >> 3) & 1) * 8;
    const int l_r0 = tid >> 3, l_c8 = (tid & 7) << 3;

    float acc[2][8][4];
#pragma unroll
    for (int i = 0; i < 2; i++)
#pragma unroll
        for (int j = 0; j < 8; j++)
#pragma unroll
            for (int d = 0; d < 4; d++) acc[i][j][d] = 0.f;

    const int nch = K >> 6;

#define ISSUE_H(cc, ss) do {                                                  \
    uint32_t sbase = sb + (ss) * STGK_BYTES;                                  \
    _Pragma("unroll")                                                         \
    for (int i_ = 0; i_ < 4; i_++) {                                          \
        int r_ = l_r0 + i_ * 32;                                              \
        uint32_t so_ = sbase + (uint32_t)(r_ * 72 + l_c8) * 2;                \
        size_t ga_ = (size_t)(row0 + r_) * K + (cc) * 64 + l_c8;              \
        size_t gb_ = (size_t)(col0 + r_) * K + (cc) * 64 + l_c8;              \
        cp16(so_,             A + ga_);                                       \
        cp16(so_ + 2*PARTK,   B + gb_);                                       \
    }                                                                         \
    CP_COMMIT();                                                              \
} while (0)

#define LOAD_FRAGS(ksv, buf) do {                                             \
    _Pragma("unroll")                                                         \
    for (int mi_ = 0; mi_ < 2; mi_++)                                         \
        LDSM4(ah[buf][mi_], aoff + mi_ * 2304 + (ksv) * 32);                  \
    _Pragma("unroll")                                                         \
    for (int ng_ = 0; ng_ < 4; ng_++)                                         \
        LDSM4(bf[buf][ng_], boff + ng_ * 2304 + (ksv) * 32);                  \
} while (0)

    ISSUE_H(0, 0);
    ISSUE_H(1, 1);

    for (int c = 0; c < nch; ++c) {
        if (c == nch - 1) { CP_WAIT0(); } else { CP_WAIT1(); }
        __syncthreads();
        // refill the stage freed at iter c-1 BEFORE computing (early issue)
        if (c + 2 < nch) {
            int ns = c + 2; ns -= (ns / 3) * 3;    // (c+2)%3
            ISSUE_H(c + 2, ns);
        }
        {
            int cs = c; cs -= (cs / 3) * 3;        // c%3
            const uint32_t base = sb + cs * STGK_BYTES;
            const uint32_t aoff = base + 2 * ((wy * 32 + a_rl) * 72 + a_ko);
            const uint32_t boff = base + 2 * PARTK
                                  + 2 * ((wx * 64 + b_nl) * 72 + b_ko);
            uint32_t ah[2][2][4], bf[2][4][4];     // [buf][...]
            LOAD_FRAGS(0, 0);
#pragma unroll
            for (int ks = 0; ks < 4; ks++) {
                const int cur = ks & 1, nxt = cur ^ 1;
                if (ks < 3) LOAD_FRAGS(ks + 1, nxt);
#pragma unroll
                for (int ng = 0; ng < 4; ng++) {
#pragma unroll
                    for (int mi = 0; mi < 2; mi++) {
                        MMAH16816(acc[mi][ng*2],   ah[cur][mi],
                                  bf[cur][ng][0], bf[cur][ng][1]);
                        MMAH16816(acc[mi][ng*2+1], ah[cur][mi],
                                  bf[cur][ng][2], bf[cur][ng][3]);
                    }
                }
            }
        }
    }

#pragma unroll
    for (int mi = 0; mi < 2; mi++) {
#pragma unroll
        for (int ni = 0; ni < 8; ni++) {
            int rr = row0 + wy * 32 + mi * 16 + (lane >> 2);
            int cc = col0 + wx * 64 + ni * 8 + (lane & 3) * 2;
            float2 v0 = {acc[mi][ni][0], acc[mi][ni][1]};
            float2 v1 = {acc[mi][ni][2], acc[mi][ni][3]};
            if (bias) {
                float bx = bias[cc], by = bias[cc + 1];
                v0.x += bx; v0.y += by; v1.x += bx; v1.y += by;
            }
            *(float2*)(C + (size_t)rr * N + cc) = v0;
            *(float2*)(C + (size_t)(rr + 8) * N + cc) = v1;
        }
    }
}

// ====== phi: 8x8-tile microkernel; inputs arrive PRE-SCALED (W folded) =====
#define PHI_XT_OFF   0
#define PHI_OM_OFF   (64*132)
#define PHI_NRM_OFF  (2*64*132)
#define PHI_WM_OFF   (PHI_NRM_OFF + 128)
#define PHI_SMEM_BYTES ((PHI_WM_OFF + 8) * 4)

__global__ void __launch_bounds__(256, 2) phi2_kernel(
    const float* __restrict__ srcq, const float* __restrict__ srck,
    const float* __restrict__ omega,
    __half* __restrict__ dstq16, float* __restrict__ dstk)
{
    extern __shared__ float smf[];
    float* sXT  = smf + PHI_XT_OFF;
    float* sOmT = smf + PHI_OM_OFF;
    float* sNrm = smf + PHI_NRM_OFF;
    float* sWm  = smf + PHI_WM_OFF;

    const bool isq = (blockIdx.z == 0);
    const float* src = isq ? srcq : srck;

    const int tid = threadIdx.x;
    const int bh = blockIdx.y, b = bh >> 4, h = bh & 15;
    const int n0 = blockIdx.x * 128;
    const float INVSQ = 0.08838834764831845f;   // 1/sqrt(128)

    for (int i = tid; i < 128 * 16; i += 256) {          // omega^T
        int m = i & 127, kq = (i >> 7) << 2;
        float4 w = *(const float4*)&omega[m * 64 + kq];
        sOmT[(kq + 0) * 132 + m] = w.x; sOmT[(kq + 1) * 132 + m] = w.y;
        sOmT[(kq + 2) * 132 + m] = w.z; sOmT[(kq + 3) * 132 + m] = w.w;
    }
    for (int i = tid; i < 128 * 16; i += 256) {          // x^T (pre-scaled)
        int r = i & 127, kq = (i >> 7) << 2;
        float4 xv = *(const float4*)&src[(size_t)(b * SEQ + n0 + r) * EDIM + h * HDIM + kq];
        sXT[(kq + 0) * 132 + r] = xv.x; sXT[(kq + 1) * 132 + r] = xv.y;
        sXT[(kq + 2) * 132 + r] = xv.z; sXT[(kq + 3) * 132 + r] = xv.w;
    }
    __syncthreads();

    if (!isq && tid < 128) {
        float s = 0.f;
#pragma unroll 8
        for (int kk = 0; kk < 64; kk++) {
            float xv = sXT[kk * 132 + tid];
            s = fmaf(xv, xv, s);
        }
        sNrm[tid] = s;
    }

    const int tx = tid & 15, ty = tid >> 4;
    const int m0 = tx << 3, r0 = ty << 3;
    float acc[8][8];
#pragma unroll
    for (int i = 0; i < 8; i++)
#pragma unroll
        for (int j = 0; j < 8; j++) acc[i][j] = 0.f;

#pragma unroll 2
    for (int kk = 0; kk < 64; kk++) {
        float4 o0 = *(const float4*)&sOmT[kk * 132 + m0];
        float4 o1 = *(const float4*)&sOmT[kk * 132 + m0 + 4];
        float4 xa = *(const float4*)&sXT[kk * 132 + r0];
        float4 xb = *(const float4*)&sXT[kk * 132 + r0 + 4];
        float xr[8] = {xa.x, xa.y, xa.z, xa.w, xb.x, xb.y, xb.z, xb.w};
        float ov[8] = {o0.x, o0.y, o0.z, o0.w, o1.x, o1.y, o1.z, o1.w};
#pragma unroll
        for (int i = 0; i < 8; i++)
#pragma unroll
            for (int j = 0; j < 8; j++)
                acc[i][j] = fmaf(xr[i], ov[j], acc[i][j]);
    }

    if (isq) {
#pragma unroll
        for (int i = 0; i < 8; i++) {
            float mx = acc[i][0];
#pragma unroll
            for (int j = 1; j < 8; j++) mx = fmaxf(mx, acc[i][j]);
#pragma unroll
            for (int off = 8; off; off >>= 1)
                mx = fmaxf(mx, __shfl_xor_sync(0xffffffffu, mx, off));
            float o[8];
#pragma unroll
            for (int j = 0; j < 8; j++)
                o[j] = expf(acc[i][j] - mx) * INVSQ + 1e-4f;
            __half2 h0 = __floats2half2_rn(o[0], o[1]);
            __half2 h1 = __floats2half2_rn(o[2], o[3]);
            __half2 h2 = __floats2half2_rn(o[4], o[5]);
            __half2 h3 = __floats2half2_rn(o[6], o[7]);
            uint4 u = {*(uint32_t*)&h0, *(uint32_t*)&h1,
                       *(uint32_t*)&h2, *(uint32_t*)&h3};
            *(uint4*)&dstq16[((size_t)bh * SEQ + n0 + r0 + i) * MFEAT + m0] = u;
        }
    } else {
        __syncthreads();                      // sNrm ready
        float gm = -INFINITY;
#pragma unroll
        for (int i = 0; i < 8; i++) {
            float nv = 0.5f * sNrm[r0 + i];
            float4 o0, o1;
            o0.x = acc[i][0] - nv; o0.y = acc[i][1] - nv;
            o0.z = acc[i][2] - nv; o0.w = acc[i][3] - nv;
            o1.x = acc[i][4] - nv; o1.y = acc[i][5] - nv;
            o1.z = acc[i][6] - nv; o1.w = acc[i][7] - nv;
            gm = fmaxf(gm, fmaxf(fmaxf(o0.x, o0.y), fmaxf(o0.z, o0.w)));
            gm = fmaxf(gm, fmaxf(fmaxf(o1.x, o1.y), fmaxf(o1.z, o1.w)));
            size_t base = ((size_t)bh * SEQ + n0 + r0 + i) * MFEAT + m0;
            *(float4*)&dstk[base]     = o0;
            *(float4*)&dstk[base + 4] = o1;
        }
#pragma unroll
        for (int off = 16; off; off >>= 1)
            gm = fmaxf(gm, __shfl_xor_sync(0xffffffffu, gm, off));
        if ((tid & 31) == 0) sWm[tid >> 5] = gm;
        __syncthreads();
        if (tid == 0) {
            float mb = sWm[0];
#pragma unroll
            for (int i = 1; i < 8; i++) mb = fmaxf(mb, sWm[i]);
            atomicMax(&d_gmax, enc_f(mb));
        }
    }
}

// ---- step A: finalize phik (exp), emit phik16 + v16, chunk sums S / s -----
__global__ void __launch_bounds__(256) stepA_kernel(
    __half* __restrict__ phik16, __half* __restrict__ v16)
{
    __shared__ float sPk[32][128];
    __shared__ float sV[32][64];
    const int c = blockIdx.x, bh = blockIdx.y;
    const int b = bh >> 4, h = bh & 15;
    const int tid = threadIdx.x;
    const int tx = tid & 15, ty = tid >> 4;
    const int m0 = ty * 8, d0 = tx * 4;
    const float g = dec_f(d_gmax);
    const float INVSQ = 0.08838834764831845f;   // 1/sqrt(128)
    float acc[8][4] = {};
    float ss = 0.f;

    for (int nt = 0; nt < 2; nt++) {
        const int nb = c * CHUNK + nt * 32;
        __syncthreads();
        for (int i = tid; i < 32 * 32; i += 256) {
            int n = i >> 5, mq = (i & 31) * 4;
            size_t gidx = ((size_t)bh*SEQ + nb + n)*MFEAT + mq;
            float4 v4 = *(const float4*)&d_phik[gidx];
            v4.x = expf(v4.x - g) * INVSQ + 1e-4f;
            v4.y = expf(v4.y - g) * INVSQ + 1e-4f;
            v4.z = expf(v4.z - g) * INVSQ + 1e-4f;
            v4.w = expf(v4.w - g) * INVSQ + 1e-4f;
            *(float4*)&sPk[n][mq] = v4;
            __half2 h0 = __floats2half2_rn(v4.x, v4.y);
            __half2 h1 = __floats2half2_rn(v4.z, v4.w);
            uint2 u = {*(uint32_t*)&h0, *(uint32_t*)&h1};
            *(uint2*)&phik16[gidx] = u;
        }
        for (int i = tid; i < 32 * 16; i += 256) {
            int n = i >> 4, dq = (i & 15) * 4;
            size_t vidx = ((size_t)(b*SEQ + nb + n))*EDIM + h*HDIM + dq;
            float4 vv = *(const float4*)&d_v[vidx];
            *(float4*)&sV[n][dq] = vv;
            __half2 h0 = __floats2half2_rn(vv.x, vv.y);
            __half2 h1 = __floats2half2_rn(vv.z, vv.w);
            uint2 u = {*(uint32_t*)&h0, *(uint32_t*)&h1};
            *(uint2*)&v16[vidx] = u;
        }
        __syncthreads();
        for (int n = 0; n < 32; n++) {
            float4 p0 = *(const float4*)&sPk[n][m0];
            float4 p1 = *(const float4*)&sPk[n][m0 + 4];
            float4 vv = *(const float4*)&sV[n][d0];
            float pm[8] = {p0.x,p0.y,p0.z,p0.w,p1.x,p1.y,p1.z,p1.w};
            float vd[4] = {vv.x,vv.y,vv.z,vv.w};
#pragma unroll
            for (int i = 0; i < 8; i++)
#pragma unroll
                for (int j = 0; j < 4; j++)
                    acc[i][j] = fmaf(pm[i], vd[j], acc[i][j]);
        }
        if (tid < 128) {
#pragma unroll
            for (int n = 0; n < 32; n++) ss += sPk[n][tid];
        }
    }
    size_t base = ((size_t)bh * NCHUNK + c) * MFEAT;
#pragma unroll
    for (int i = 0; i < 8; i++) {
        float4 o = {acc[i][0], acc[i][1], acc[i][2], acc[i][3]};
        *(float4*)&d_Ssum[(base + m0 + i) * HDIM + d0] = o;
    }
    if (tid < 128) d_ssum[base + tid] = ss;
}

// ------- step B: exclusive prefix over chunks -> fp16 KVpre ----------------
__global__ void __launch_bounds__(256) stepB_kernel(__half* __restrict__ kvp16)
{
    const int bh = blockIdx.x, ds = blockIdx.y;     // ds in 0..3
    const int tid = threadIdx.x;
    const int m = tid >> 1, dq = ds * 16 + (tid & 1) * 8;
    float run[8] = {};
    float sr = 0.f;
    const bool do_s = (ds == 0) && ((tid & 1) == 0);

    size_t base = ((size_t)bh * NCHUNK) * MFEAT;
    size_t off0 = (base + m) * HDIM + dq;
    float4 p0 = *(const float4*)&d_Ssum[off0];
    float4 p1 = *(const float4*)&d_Ssum[off0 + 4];
    float ps = do_s ? d_ssum[base + m] : 0.f;

    for (int c = 0; c < NCHUNK; c++) {
        float4 c0 = p0, c1 = p1; float cs = ps;
        size_t cbase = base + (size_t)c * MFEAT;
        size_t coff = (cbase + m) * HDIM + dq;
        if (c + 1 < NCHUNK) {
            size_t noff = coff + (size_t)MFEAT * HDIM;
            p0 = *(const float4*)&d_Ssum[noff];
            p1 = *(const float4*)&d_Ssum[noff + 4];
            if (do_s) ps = d_ssum[cbase + MFEAT + m];
        }
        __half2 h0 = __floats2half2_rn(run[0], run[1]);
        __half2 h1 = __floats2half2_rn(run[2], run[3]);
        __half2 h2 = __floats2half2_rn(run[4], run[5]);
        __half2 h3 = __floats2half2_rn(run[6], run[7]);
        uint4 u = {*(uint32_t*)&h0, *(uint32_t*)&h1,
                   *(uint32_t*)&h2, *(uint32_t*)&h3};
        *(uint4*)&kvp16[coff] = u;
        run[0] += c0.x; run[1] += c0.y; run[2] += c0.z; run[3] += c0.w;
        run[4] += c1.x; run[5] += c1.y; run[6] += c1.z; run[7] += c1.w;
        if (do_s) {
            d_spre[cbase + m] = sr;
            sr += cs;
        }
    }
}

// ------- step C (tensorized): A=phiq@phik^T (masked), O=A@V + phiq@KVpre ---
#define SC_Q   0
#define SC_K   (64*136)
#define SC_A   (2*64*136)
#define SC_VT  (SC_A + 64*72)
#define SC_KT  (SC_VT + 64*72)
#define SC_HEND (SC_KT + 64*136)             /* 35328 halves */
#define SC_SMEM_BYTES (SC_HEND*2 + 256*4)    /* + 256 floats = 71680 B */

__global__ void __launch_bounds__(256, 2) stepC_kernel(
    const __half* __restrict__ phiq16, const __half* __restrict__ phik16,
    const __half* __restrict__ v16, const __half* __restrict__ kvp16,
    __half* __restrict__ oh)
{
    extern __shared__ __half sm16[];
    float* smf = (float*)(sm16 + SC_HEND);
    float* sZ  = smf;
    float* sZ2 = smf + 64;
    float* sSp = smf + 128;

    const int c = blockIdx.x, bh = blockIdx.y;
    const int b = bh >> 4, h = bh & 15;
    const int tid = threadIdx.x, wid = tid >> 5, lane = tid & 31;
    const int wy = wid & 1, wx = wid >> 1;          // 2(M) x 4(N)
    const int n0 = c * CHUNK;
    const uint32_t sb = smem_u32(sm16);

    const int a_rl = lane & 15, a_ko = (lane >> 4) * 8;
    const int b_nl = (lane & 7) + (lane >> 4) * 8, b_ko = ((lane >> 3) & 1) * 8;

    if (tid < 128) { sZ[tid & 63] = 0.f; sZ2[tid & 63] = 0.f; }
    for (int i = tid; i < 1024; i += 256) {
        int r = i >> 4, seg = (i & 15) * 8;
        size_t gq = ((size_t)bh*SEQ + n0 + r)*MFEAT + seg;
        *(uint4*)&sm16[SC_Q + r*136 + seg] = *(const uint4*)&phiq16[gq];
        *(uint4*)&sm16[SC_K + r*136 + seg] = *(const uint4*)&phik16[gq];
    }
    for (int i = tid; i < 4096; i += 256) {
        int d = i & 63, j = i >> 6;
        sm16[SC_VT + d*72 + j] =
            v16[((size_t)(b*SEQ + n0 + j))*EDIM + h*HDIM + d];
    }
    {
        size_t kb = ((size_t)bh * NCHUNK + c) * MFEAT;
        for (int i = tid; i < 8192; i += 256) {
            int d = i & 63, m = i >> 6;
            sm16[SC_KT + d*136 + m] = kvp16[(kb + m)*HDIM + d];
        }
        if (tid < 128) sSp[tid] = d_spre[kb + tid];
    }
    __syncthreads();

    float accA[2][2][4];
#pragma unroll
    for (int i = 0; i < 2; i++)
#pragma unroll
        for (int j = 0; j < 2; j++)
#pragma unroll
            for (int d = 0; d < 4; d++) accA[i][j][d] = 0.f;

    const uint32_t qb = sb + SC_Q*2, kbb = sb + SC_K*2;
#pragma unroll
    for (int ks = 0; ks < 8; ks++) {
        uint32_t ah[2][4];
#pragma unroll
        for (int mi = 0; mi < 2; mi++)
            LDSM4(ah[mi], qb + (wy*32 + mi*16 + a_rl)*272 + (ks*16 + a_ko)*2);
        uint32_t bfr[4];
        LDSM4(bfr, kbb + (wx*16 + b_nl)*272 + (ks*16 + b_ko)*2);
#pragma unroll
        for (int mi = 0; mi < 2; mi++) {
            MMAH16816(accA[mi][0], ah[mi], bfr[0], bfr[1]);
            MMAH16816(accA[mi][1], ah[mi], bfr[2], bfr[3]);
        }
    }

#pragma unroll
    for (int mi = 0; mi < 2; mi++) {
        int r0 = wy*32 + mi*16 + (lane >> 2);
        int r1 = r0 + 8;
        float z0 = 0.f, z1 = 0.f;
#pragma unroll
        for (int ng = 0; ng < 2; ng++) {
            int cc = wx*16 + ng*8 + (lane & 3)*2;
            float a0 = (cc     <= r0) ? accA[mi][ng][0] : 0.f;
            float a1 = (cc + 1 <= r0) ? accA[mi][ng][1] : 0.f;
            float a2 = (cc     <= r1) ? accA[mi][ng][2] : 0.f;
            float a3 = (cc + 1 <= r1) ? accA[mi][ng][3] : 0.f;
            z0 += a0 + a1; z1 += a2 + a3;
            __half2 h01 = __floats2half2_rn(a0, a1);
            __half2 h23 = __floats2half2_rn(a2, a3);
            *(__half2*)&sm16[SC_A + r0*72 + cc] = h01;
            *(__half2*)&sm16[SC_A + r1*72 + cc] = h23;
        }
        z0 += __shfl_xor_sync(0xffffffffu, z0, 1);
        z0 += __shfl_xor_sync(0xffffffffu, z0, 2);
        z1 += __shfl_xor_sync(0xffffffffu, z1, 1);
        z1 += __shfl_xor_sync(0xffffffffu, z1, 2);
        if ((lane & 3) == 0) {
            atomicAdd(&sZ[r0], z0);
            atomicAdd(&sZ[r1], z1);
        }
    }
    __syncthreads();

    float acc[2][2][4];
#pragma unroll
    for (int i = 0; i < 2; i++)
#pragma unroll
        for (int j = 0; j < 2; j++)
#pragma unroll
            for (int d = 0; d < 4; d++) acc[i][j][d] = 0.f;

    const uint32_t ab = sb + SC_A*2, vtb = sb + SC_VT*2, ktb = sb + SC_KT*2;
#pragma unroll
    for (int ks = 0; ks < 4; ks++) {
        uint32_t ah[2][4];
#pragma unroll
        for (int mi = 0; mi < 2; mi++)
            LDSM4(ah[mi], ab + (wy*32 + mi*16 + a_rl)*144 + (ks*16 + a_ko)*2);
        uint32_t bfr[4];
        LDSM4(bfr, vtb + (wx*16 + b_nl)*144 + (ks*16 + b_ko)*2);
#pragma unroll
        for (int mi = 0; mi < 2; mi++) {
            MMAH16816(acc[mi][0], ah[mi], bfr[0], bfr[1]);
            MMAH16816(acc[mi][1], ah[mi], bfr[2], bfr[3]);
        }
    }
#pragma unroll
    for (int ks = 0; ks < 8; ks++) {
        uint32_t ah[2][4];
#pragma unroll
        for (int mi = 0; mi < 2; mi++)
            LDSM4(ah[mi], qb + (wy*32 + mi*16 + a_rl)*272 + (ks*16 + a_ko)*2);
        uint32_t bfr[4];
        LDSM4(bfr, ktb + (wx*16 + b_nl)*272 + (ks*16 + b_ko)*2);
#pragma unroll
        for (int mi = 0; mi < 2; mi++) {
            MMAH16816(acc[mi][0], ah[mi], bfr[0], bfr[1]);
            MMAH16816(acc[mi][1], ah[mi], bfr[2], bfr[3]);
        }
    }

    if (tid < 64) {
        float z = 0.f;
#pragma unroll 8
        for (int mm = 0; mm < 64; mm++) {
            __half2 qq = *(__half2*)&sm16[SC_Q + tid*136 + mm*2];
            float2 qf = __half22float2(qq);
            z = fmaf(qf.x, sSp[mm*2],     z);
            z = fmaf(qf.y, sSp[mm*2 + 1], z);
        }
        sZ2[tid] = z;
    }
    __syncthreads();

#pragma unroll
    for (int mi = 0; mi < 2; mi++) {
        int r0 = wy*32 + mi*16 + (lane >> 2);
        int r1 = r0 + 8;
        float inv0 = 1.f / (sZ[r0] + sZ2[r0] + 1e-6f);
        float inv1 = 1.f / (sZ[r1] + sZ2[r1] + 1e-6f);
#pragma unroll
        for (int ng = 0; ng < 2; ng++) {
            int cc = wx*16 + ng*8 + (lane & 3)*2;
            __half2 h0 = __floats2half2_rn(acc[mi][ng][0]*inv0, acc[mi][ng][1]*inv0);
            __half2 h1 = __floats2half2_rn(acc[mi][ng][2]*inv1, acc[mi][ng][3]*inv1);
            *(__half2*)&oh[((size_t)(b*SEQ + n0 + r0))*EDIM + h*HDIM + cc] = h0;
            *(__half2*)&oh[((size_t)(b*SEQ + n0 + r1))*EDIM + h*HDIM + cc] = h1;
        }
    }
}

// ---------------- host launcher --------------------------------------------
extern "C" void kernel_launch(void* const* d_in, const int* in_sizes, int n_in,
                              void* d_out, int out_size)
{
    const float* x     = (const float*)d_in[0];
    const float* omega = (const float*)d_in[1];
    const float* Wq    = (const float*)d_in[2];
    const float* Wk    = (const float*)d_in[3];
    const float* Wv    = (const float*)d_in[4];
    const float* Wo    = (const float*)d_in[5];
    const float* bo    = (const float*)d_in[6];
    float* out = (float*)d_out;

    float *q, *k, *v, *phik;
    cudaGetSymbolAddress((void**)&q,    d_q);
    cudaGetSymbolAddress((void**)&k,    d_k);
    cudaGetSymbolAddress((void**)&v,    d_v);
    cudaGetSymbolAddress((void**)&phik, d_phik);

    __half *x16, *wq16, *wk16, *wv16, *wo16, *at16, *pq16, *pk16, *kvp16;
    cudaGetSymbolAddress((void**)&x16,   d_x16);
    cudaGetSymbolAddress((void**)&wq16,  d_wq16);
    cudaGetSymbolAddress((void**)&wk16,  d_wk16);
    cudaGetSymbolAddress((void**)&wv16,  d_wv16);
    cudaGetSymbolAddress((void**)&wo16,  d_wo16);
    cudaGetSymbolAddress((void**)&at16,  d_at16);
    cudaGetSymbolAddress((void**)&pq16,  d_phiq16);
    cudaGetSymbolAddress((void**)&pk16,  d_phik16);
    cudaGetSymbolAddress((void**)&kvp16, d_kvp16);

    const int SMEM_MMA = 3 * STGK_BYTES;                        // 110592
    cudaFuncSetAttribute(mma_gemm_h,
                         cudaFuncAttributeMaxDynamicSharedMemorySize, SMEM_MMA);
    cudaFuncSetAttribute(phi2_kernel,
                         cudaFuncAttributeMaxDynamicSharedMemorySize, PHI_SMEM_BYTES);
    cudaFuncSetAttribute(stepC_kernel,
                         cudaFuncAttributeMaxDynamicSharedMemorySize, SC_SMEM_BYTES);

    // launches 1-3 (4th = the QKV GEMM -> ncu capture slot)
    reset_kernel<<<1, 1>>>();
    cvt_x_kernel<<<(BATCH*SEQ*EDIM/4)/256, 256>>>(x, x16);
    cvt_w4_kernel<<<dim3((EDIM*EDIM/4)/256, 4), 256>>>(
        Wq, Wk, Wv, Wo, wq16, wk16, wv16, wo16);

    // launch 4: fused QKV projection (fp16 1-term, frag double-buffered)
    mma_gemm_h<<<dim3(EDIM/128, (BATCH*SEQ)/128, 3), 256, SMEM_MMA>>>(
        x16, wq16, wk16, wv16, q, k, v, nullptr, EDIM, EDIM);

    // phi features (q,k arrive pre-scaled; q -> fp16, k -> raw log fp32)
    phi2_kernel<<<dim3(SEQ/128, BH, 2), 256, PHI_SMEM_BYTES>>>(
        q, k, omega, pq16, phik);

    // chunked causal linear attention
    stepA_kernel<<<dim3(NCHUNK, BH), 256>>>(pk16, x16);
    stepB_kernel<<<dim3(BH, 4), 256>>>(kvp16);
    stepC_kernel<<<dim3(NCHUNK, BH), 256, SC_SMEM_BYTES>>>(
        pq16, pk16, x16, kvp16, at16);

    // output projection + bias (fp16 1-term, frag double-buffered)
    mma_gemm_h<<<dim3(EDIM/128, (BATCH*SEQ)/128, 1), 256, SMEM_MMA>>>(
        at16, wo16, wo16, wo16, out, out, out, bo, EDIM, EDIM);
}

// round 17
// speedup vs baseline: 1.0330x; 1.0330x over previous
#include <cuda_runtime.h>
#include <cuda_fp16.h>
#include <math.h>
#include <stdint.h>

#define BATCH 2
#define SEQ   1024
#define EDIM  1024
#define HEADS 16
#define HDIM  64
#define MFEAT 128
#define BH    (BATCH*HEADS)     /* 32 */
#define CHUNK 64
#define NCHUNK (SEQ/CHUNK)      /* 16 */

// ---------------- scratch (device globals: no allocation allowed) ----------
__device__ float d_q[BATCH*SEQ*EDIM];
__device__ float d_k[BATCH*SEQ*EDIM];
__device__ float d_v[BATCH*SEQ*EDIM];
__device__ float d_phik[BH*SEQ*MFEAT];           // raw log-phik (phi -> stepA)
__device__ float d_Ssum[BH*NCHUNK*MFEAT*HDIM];
__device__ float d_ssum[BH*NCHUNK*MFEAT];
__device__ float d_spre[BH*NCHUNK*MFEAT];
__device__ unsigned d_gmax;

// fp16 scratch
__device__ __half d_x16[BATCH*SEQ*EDIM];         // x16 for QKV, then v16
__device__ __half d_wq16[EDIM*EDIM], d_wk16[EDIM*EDIM];
__device__ __half d_wv16[EDIM*EDIM], d_wo16[EDIM*EDIM];
__device__ __half d_at16[BATCH*SEQ*EDIM];
__device__ __half d_phiq16[BH*SEQ*MFEAT];
__device__ __half d_phik16[BH*SEQ*MFEAT];
__device__ __half d_kvp16[BH*NCHUNK*MFEAT*HDIM];

// ordered-float <-> uint monotone mapping for atomicMax on floats
__device__ __forceinline__ unsigned enc_f(float f) {
    unsigned u = __float_as_uint(f);
    return (u & 0x80000000u) ? ~u : (u | 0x80000000u);
}
__device__ __forceinline__ float dec_f(unsigned u) {
    return (u & 0x80000000u) ? __uint_as_float(u ^ 0x80000000u)
                             : __uint_as_float(~u);
}

__global__ void reset_kernel() { d_gmax = 0x007FFFFFu; /* enc(-inf) */ }

// ============================ mma.sync helpers ==============================
__device__ __forceinline__ uint32_t smem_u32(const void* p) {
    uint32_t a;
    asm("{ .reg .u64 t; cvta.to.shared.u64 t, %1; cvt.u32.u64 %0, t; }"
        : "=r"(a) : "l"(p));
    return a;
}

#define LDSM4(r, a) \
    asm volatile("ldmatrix.sync.aligned.m8n8.x4.shared.b16 {%0,%1,%2,%3}, [%4];" \
        : "=r"((r)[0]), "=r"((r)[1]), "=r"((r)[2]), "=r"((r)[3]) : "r"(a))

#define MMAH16816(d, a, b0, b1) \
    asm volatile("mma.sync.aligned.m16n8k16.row.col.f32.f16.f16.f32 " \
        "{%0,%1,%2,%3}, {%4,%5,%6,%7}, {%8,%9}, {%0,%1,%2,%3};" \
        : "+f"((d)[0]), "+f"((d)[1]), "+f"((d)[2]), "+f"((d)[3]) \
        : "r"((a)[0]), "r"((a)[1]), "r"((a)[2]), "r"((a)[3]), \
          "r"(b0), "r"(b1))

__device__ __forceinline__ void cp16(uint32_t d, const void* s) {
    asm volatile("cp.async.cg.shared.global [%0], [%1], 16;" :: "r"(d), "l"(s));
}
#define CP_COMMIT() asm volatile("cp.async.commit_group;" ::: "memory")
#define CP_WAIT1()  asm volatile("cp.async.wait_group 1;" ::: "memory")
#define CP_WAIT0()  asm volatile("cp.async.wait_group 0;" ::: "memory")

// ------- pre-pass: x -> fp16 -------------------------------------------------
__global__ void __launch_bounds__(256) cvt_x_kernel(
    const float* __restrict__ x, __half* __restrict__ x16)
{
    size_t i = (size_t)blockIdx.x * 256 + threadIdx.x;
    float4 v = *((const float4*)x + i);
    __half2 a = __floats2half2_rn(v.x, v.y);
    __half2 b = __floats2half2_rn(v.z, v.w);
    uint2 u; u.x = *(uint32_t*)&a; u.y = *(uint32_t*)&b;
    *(uint2*)(x16 + i * 4) = u;
}

// ------- pre-pass: 4 weights -> fp16; Wq/Wk pre-scaled by 64^-0.25 ----------
__global__ void __launch_bounds__(256) cvt_w4_kernel(
    const float* __restrict__ s0, const float* __restrict__ s1,
    const float* __restrict__ s2, const float* __restrict__ s3,
    __half* __restrict__ w0, __half* __restrict__ w1,
    __half* __restrict__ w2, __half* __restrict__ w3)
{
    const float* src = s0; __half* w = w0;
    float sc = 0.35355339059327373f;                 // Wq scaled
    if (blockIdx.y == 1) { src = s1; w = w1; }       // Wk scaled
    if (blockIdx.y == 2) { src = s2; w = w2; sc = 1.f; }
    if (blockIdx.y == 3) { src = s3; w = w3; sc = 1.f; }
    size_t i = (size_t)blockIdx.x * 256 + threadIdx.x;
    float4 v = *((const float4*)src + i);
    __half2 a = __floats2half2_rn(v.x * sc, v.y * sc);
    __half2 b = __floats2half2_rn(v.z * sc, v.w * sc);
    uint2 u; u.x = *(uint32_t*)&a; u.y = *(uint32_t*)&b;
    *(uint2*)(w + i * 4) = u;
}

// ====== fp16 1-term GEMM: C = A @ B^T (+bias), both single fp16 =============
// CTA tile 128x128, K-chunk 64 (144B rows, conflict-free ldmatrix), 3-stage
// cp.async, 2 CTAs/SM, one barrier per chunk. 8 warps, warp tile 32x64.
#define PARTK 9216                           /* 128*72 elems per part */
#define STGK_BYTES (2 * PARTK * 2)           /* A+B parts = 36864 B */

__global__ void __launch_bounds__(256, 2) mma_gemm_h(
    const __half* __restrict__ A,
    const __half* __restrict__ B0, const __half* __restrict__ B1,
    const __half* __restrict__ B2,
    float* __restrict__ C0, float* __restrict__ C1, float* __restrict__ C2,
    const float* __restrict__ bias, int N, int K)
{
    extern __shared__ __half smh[];
    const __half* B = B0; float* C = C0;
    if (blockIdx.z == 1) { B = B1; C = C1; }
    if (blockIdx.z == 2) { B = B2; C = C2; }

    const int tid = threadIdx.x, wid = tid >> 5, lane = tid & 31;
    const int wy = wid & 3, wx = wid >> 2;          // warp grid 4(M) x 2(N)
    const int row0 = blockIdx.y * 128, col0 = blockIdx.x * 128;
    const uint32_t sb = smem_u32(smh);

    const int a_rl = lane & 15, a_ko = (lane >> 4) * 8;
    const int b_nl = (lane & 7) + (lane >> 4) * 8, b_ko = ((lane >> 3) & 1) * 8;
    const int l_r0 = tid >> 3, l_c8 = (tid & 7) << 3;

    float acc[2][8][4];
#pragma unroll
    for (int i = 0; i < 2; i++)
#pragma unroll
        for (int j = 0; j < 8; j++)
#pragma unroll
            for (int d = 0; d < 4; d++) acc[i][j][d] = 0.f;

    const int nch = K >> 6;

#define ISSUE_H(cc, ss) do {                                                  \
    uint32_t sbase = sb + (ss) * STGK_BYTES;                                  \
    _Pragma("unroll")                                                         \
    for (int i_ = 0; i_ < 4; i_++) {                                          \
        int r_ = l_r0 + i_ * 32;                                              \
        uint32_t so_ = sbase + (uint32_t)(r_ * 72 + l_c8) * 2;                \
        size_t ga_ = (size_t)(row0 + r_) * K + (cc) * 64 + l_c8;              \
        size_t gb_ = (size_t)(col0 + r_) * K + (cc) * 64 + l_c8;              \
        cp16(so_,             A + ga_);                                       \
        cp16(so_ + 2*PARTK,   B + gb_);                                       \
    }                                                                         \
    CP_COMMIT();                                                              \
} while (0)

    ISSUE_H(0, 0);
    ISSUE_H(1, 1);

    for (int c = 0; c < nch; ++c) {
        if (c == nch - 1) { CP_WAIT0(); } else { CP_WAIT1(); }
        __syncthreads();
        // refill the stage freed at iter c-1 BEFORE computing (early issue)
        if (c + 2 < nch) {
            int ns = c + 2; ns -= (ns / 3) * 3;    // (c+2)%3
            ISSUE_H(c + 2, ns);
        }
        {
            int cs = c; cs -= (cs / 3) * 3;        // c%3
            const uint32_t base = sb + cs * STGK_BYTES;
            const uint32_t aoff = base + 2 * ((wy * 32 + a_rl) * 72 + a_ko);
            const uint32_t boff = base + 2 * PARTK
                                  + 2 * ((wx * 64 + b_nl) * 72 + b_ko);
#pragma unroll
            for (int ks = 0; ks < 4; ks++) {
                uint32_t ah[2][4];
#pragma unroll
                for (int mi = 0; mi < 2; mi++)
                    LDSM4(ah[mi], aoff + mi * 2304 + ks * 32);
#pragma unroll
                for (int ng = 0; ng < 4; ng++) {
                    uint32_t bhf[4];
                    LDSM4(bhf, boff + ng * 2304 + ks * 32);
#pragma unroll
                    for (int mi = 0; mi < 2; mi++) {
                        MMAH16816(acc[mi][ng*2],   ah[mi], bhf[0], bhf[1]);
                        MMAH16816(acc[mi][ng*2+1], ah[mi], bhf[2], bhf[3]);
                    }
                }
            }
        }
    }

#pragma unroll
    for (int mi = 0; mi < 2; mi++) {
#pragma unroll
        for (int ni = 0; ni < 8; ni++) {
            int rr = row0 + wy * 32 + mi * 16 + (lane >> 2);
            int cc = col0 + wx * 64 + ni * 8 + (lane & 3) * 2;
            float2 v0 = {acc[mi][ni][0], acc[mi][ni][1]};
            float2 v1 = {acc[mi][ni][2], acc[mi][ni][3]};
            if (bias) {
                float bx = bias[cc], by = bias[cc + 1];
                v0.x += bx; v0.y += by; v1.x += bx; v1.y += by;
            }
            *(float2*)(C + (size_t)rr * N + cc) = v0;
            *(float2*)(C + (size_t)(rr + 8) * N + cc) = v1;
        }
    }
}

// ====== phi: 8x8-tile microkernel; inputs arrive PRE-SCALED (W folded) =====
#define PHI_XT_OFF   0
#define PHI_OM_OFF   (64*132)
#define PHI_NRM_OFF  (2*64*132)
#define PHI_WM_OFF   (PHI_NRM_OFF + 128)
#define PHI_SMEM_BYTES ((PHI_WM_OFF + 8) * 4)

__global__ void __launch_bounds__(256, 2) phi2_kernel(
    const float* __restrict__ srcq, const float* __restrict__ srck,
    const float* __restrict__ omega,
    __half* __restrict__ dstq16, float* __restrict__ dstk)
{
    extern __shared__ float smf[];
    float* sXT  = smf + PHI_XT_OFF;
    float* sOmT = smf + PHI_OM_OFF;
    float* sNrm = smf + PHI_NRM_OFF;
    float* sWm  = smf + PHI_WM_OFF;

    const bool isq = (blockIdx.z == 0);
    const float* src = isq ? srcq : srck;

    const int tid = threadIdx.x;
    const int bh = blockIdx.y, b = bh >> 4, h = bh & 15;
    const int n0 = blockIdx.x * 128;
    const float INVSQ = 0.08838834764831845f;   // 1/sqrt(128)

    for (int i = tid; i < 128 * 16; i += 256) {          // omega^T
        int m = i & 127, kq = (i >> 7) << 2;
        float4 w = *(const float4*)&omega[m * 64 + kq];
        sOmT[(kq + 0) * 132 + m] = w.x; sOmT[(kq + 1) * 132 + m] = w.y;
        sOmT[(kq + 2) * 132 + m] = w.z; sOmT[(kq + 3) * 132 + m] = w.w;
    }
    for (int i = tid; i < 128 * 16; i += 256) {          // x^T (pre-scaled)
        int r = i & 127, kq = (i >> 7) << 2;
        float4 xv = *(const float4*)&src[(size_t)(b * SEQ + n0 + r) * EDIM + h * HDIM + kq];
        sXT[(kq + 0) * 132 + r] = xv.x; sXT[(kq + 1) * 132 + r] = xv.y;
        sXT[(kq + 2) * 132 + r] = xv.z; sXT[(kq + 3) * 132 + r] = xv.w;
    }
    __syncthreads();

    if (!isq && tid < 128) {
        float s = 0.f;
#pragma unroll 8
        for (int kk = 0; kk < 64; kk++) {
            float xv = sXT[kk * 132 + tid];
            s = fmaf(xv, xv, s);
        }
        sNrm[tid] = s;
    }

    const int tx = tid & 15, ty = tid >> 4;
    const int m0 = tx << 3, r0 = ty << 3;
    float acc[8][8];
#pragma unroll
    for (int i = 0; i < 8; i++)
#pragma unroll
        for (int j = 0; j < 8; j++) acc[i][j] = 0.f;

#pragma unroll 2
    for (int kk = 0; kk < 64; kk++) {
        float4 o0 = *(const float4*)&sOmT[kk * 132 + m0];
        float4 o1 = *(const float4*)&sOmT[kk * 132 + m0 + 4];
        float4 xa = *(const float4*)&sXT[kk * 132 + r0];
        float4 xb = *(const float4*)&sXT[kk * 132 + r0 + 4];
        float xr[8] = {xa.x, xa.y, xa.z, xa.w, xb.x, xb.y, xb.z, xb.w};
        float ov[8] = {o0.x, o0.y, o0.z, o0.w, o1.x, o1.y, o1.z, o1.w};
#pragma unroll
        for (int i = 0; i < 8; i++)
#pragma unroll
            for (int j = 0; j < 8; j++)
                acc[i][j] = fmaf(xr[i], ov[j], acc[i][j]);
    }

    if (isq) {
#pragma unroll
        for (int i = 0; i < 8; i++) {
            float mx = acc[i][0];
#pragma unroll
            for (int j = 1; j < 8; j++) mx = fmaxf(mx, acc[i][j]);
#pragma unroll
            for (int off = 8; off; off >>= 1)
                mx = fmaxf(mx, __shfl_xor_sync(0xffffffffu, mx, off));
            float o[8];
#pragma unroll
            for (int j = 0; j < 8; j++)
                o[j] = expf(acc[i][j] - mx) * INVSQ + 1e-4f;
            __half2 h0 = __floats2half2_rn(o[0], o[1]);
            __half2 h1 = __floats2half2_rn(o[2], o[3]);
            __half2 h2 = __floats2half2_rn(o[4], o[5]);
            __half2 h3 = __floats2half2_rn(o[6], o[7]);
            uint4 u = {*(uint32_t*)&h0, *(uint32_t*)&h1,
                       *(uint32_t*)&h2, *(uint32_t*)&h3};
            *(uint4*)&dstq16[((size_t)bh * SEQ + n0 + r0 + i) * MFEAT + m0] = u;
        }
    } else {
        __syncthreads();                      // sNrm ready
        float gm = -INFINITY;
#pragma unroll
        for (int i = 0; i < 8; i++) {
            float nv = 0.5f * sNrm[r0 + i];
            float4 o0, o1;
            o0.x = acc[i][0] - nv; o0.y = acc[i][1] - nv;
            o0.z = acc[i][2] - nv; o0.w = acc[i][3] - nv;
            o1.x = acc[i][4] - nv; o1.y = acc[i][5] - nv;
            o1.z = acc[i][6] - nv; o1.w = acc[i][7] - nv;
            gm = fmaxf(gm, fmaxf(fmaxf(o0.x, o0.y), fmaxf(o0.z, o0.w)));
            gm = fmaxf(gm, fmaxf(fmaxf(o1.x, o1.y), fmaxf(o1.z, o1.w)));
            size_t base = ((size_t)bh * SEQ + n0 + r0 + i) * MFEAT + m0;
            *(float4*)&dstk[base]     = o0;
            *(float4*)&dstk[base + 4] = o1;
        }
#pragma unroll
        for (int off = 16; off; off >>= 1)
            gm = fmaxf(gm, __shfl_xor_sync(0xffffffffu, gm, off));
        if ((tid & 31) == 0) sWm[tid >> 5] = gm;
        __syncthreads();
        if (tid == 0) {
            float mb = sWm[0];
#pragma unroll
            for (int i = 1; i < 8; i++) mb = fmaxf(mb, sWm[i]);
            atomicMax(&d_gmax, enc_f(mb));
        }
    }
}

// ---- step A: finalize phik (exp), emit phik16 + v16, chunk sums S / s -----
__global__ void __launch_bounds__(256) stepA_kernel(
    __half* __restrict__ phik16, __half* __restrict__ v16)
{
    __shared__ float sPk[32][128];
    __shared__ float sV[32][64];
    const int c = blockIdx.x, bh = blockIdx.y;
    const int b = bh >> 4, h = bh & 15;
    const int tid = threadIdx.x;
    const int tx = tid & 15, ty = tid >> 4;
    const int m0 = ty * 8, d0 = tx * 4;
    const float g = dec_f(d_gmax);
    const float INVSQ = 0.08838834764831845f;   // 1/sqrt(128)
    float acc[8][4] = {};
    float ss = 0.f;

    for (int nt = 0; nt < 2; nt++) {
        const int nb = c * CHUNK + nt * 32;
        __syncthreads();
        for (int i = tid; i < 32 * 32; i += 256) {
            int n = i >> 5, mq = (i & 31) * 4;
            size_t gidx = ((size_t)bh*SEQ + nb + n)*MFEAT + mq;
            float4 v4 = *(const float4*)&d_phik[gidx];
            v4.x = expf(v4.x - g) * INVSQ + 1e-4f;
            v4.y = expf(v4.y - g) * INVSQ + 1e-4f;
            v4.z = expf(v4.z - g) * INVSQ + 1e-4f;
            v4.w = expf(v4.w - g) * INVSQ + 1e-4f;
            *(float4*)&sPk[n][mq] = v4;
            __half2 h0 = __floats2half2_rn(v4.x, v4.y);
            __half2 h1 = __floats2half2_rn(v4.z, v4.w);
            uint2 u = {*(uint32_t*)&h0, *(uint32_t*)&h1};
            *(uint2*)&phik16[gidx] = u;
        }
        for (int i = tid; i < 32 * 16; i += 256) {
            int n = i >> 4, dq = (i & 15) * 4;
            size_t vidx = ((size_t)(b*SEQ + nb + n))*EDIM + h*HDIM + dq;
            float4 vv = *(const float4*)&d_v[vidx];
            *(float4*)&sV[n][dq] = vv;
            __half2 h0 = __floats2half2_rn(vv.x, vv.y);
            __half2 h1 = __floats2half2_rn(vv.z, vv.w);
            uint2 u = {*(uint32_t*)&h0, *(uint32_t*)&h1};
            *(uint2*)&v16[vidx] = u;
        }
        __syncthreads();
        for (int n = 0; n < 32; n++) {
            float4 p0 = *(const float4*)&sPk[n][m0];
            float4 p1 = *(const float4*)&sPk[n][m0 + 4];
            float4 vv = *(const float4*)&sV[n][d0];
            float pm[8] = {p0.x,p0.y,p0.z,p0.w,p1.x,p1.y,p1.z,p1.w};
            float vd[4] = {vv.x,vv.y,vv.z,vv.w};
#pragma unroll
            for (int i = 0; i < 8; i++)
#pragma unroll
                for (int j = 0; j < 4; j++)
                    acc[i][j] = fmaf(pm[i], vd[j], acc[i][j]);
        }
        if (tid < 128) {
#pragma unroll
            for (int n = 0; n < 32; n++) ss += sPk[n][tid];
        }
    }
    size_t base = ((size_t)bh * NCHUNK + c) * MFEAT;
#pragma unroll
    for (int i = 0; i < 8; i++) {
        float4 o = {acc[i][0], acc[i][1], acc[i][2], acc[i][3]};
        *(float4*)&d_Ssum[(base + m0 + i) * HDIM + d0] = o;
    }
    if (tid < 128) d_ssum[base + tid] = ss;
}

// ------- step B: exclusive prefix over chunks -> fp16 KVpre ----------------
__global__ void __launch_bounds__(256) stepB_kernel(__half* __restrict__ kvp16)
{
    const int bh = blockIdx.x, ds = blockIdx.y;     // ds in 0..3
    const int tid = threadIdx.x;
    const int m = tid >> 1, dq = ds * 16 + (tid & 1) * 8;
    float run[8] = {};
    float sr = 0.f;
    const bool do_s = (ds == 0) && ((tid & 1) == 0);

    size_t base = ((size_t)bh * NCHUNK) * MFEAT;
    size_t off0 = (base + m) * HDIM + dq;
    float4 p0 = *(const float4*)&d_Ssum[off0];
    float4 p1 = *(const float4*)&d_Ssum[off0 + 4];
    float ps = do_s ? d_ssum[base + m] : 0.f;

    for (int c = 0; c < NCHUNK; c++) {
        float4 c0 = p0, c1 = p1; float cs = ps;
        size_t cbase = base + (size_t)c * MFEAT;
        size_t coff = (cbase + m) * HDIM + dq;
        if (c + 1 < NCHUNK) {
            size_t noff = coff + (size_t)MFEAT * HDIM;
            p0 = *(const float4*)&d_Ssum[noff];
            p1 = *(const float4*)&d_Ssum[noff + 4];
            if (do_s) ps = d_ssum[cbase + MFEAT + m];
        }
        __half2 h0 = __floats2half2_rn(run[0], run[1]);
        __half2 h1 = __floats2half2_rn(run[2], run[3]);
        __half2 h2 = __floats2half2_rn(run[4], run[5]);
        __half2 h3 = __floats2half2_rn(run[6], run[7]);
        uint4 u = {*(uint32_t*)&h0, *(uint32_t*)&h1,
                   *(uint32_t*)&h2, *(uint32_t*)&h3};
        *(uint4*)&kvp16[coff] = u;
        run[0] += c0.x; run[1] += c0.y; run[2] += c0.z; run[3] += c0.w;
        run[4] += c1.x; run[5] += c1.y; run[6] += c1.z; run[7] += c1.w;
        if (do_s) {
            d_spre[cbase + m] = sr;
            sr += cs;
        }
    }
}

// ------- step C (tensorized): A=phiq@phik^T (masked), O=A@V + phiq@KVpre ---
#define SC_Q   0
#define SC_K   (64*136)
#define SC_A   (2*64*136)
#define SC_VT  (SC_A + 64*72)
#define SC_KT  (SC_VT + 64*72)
#define SC_HEND (SC_KT + 64*136)             /* 35328 halves */
#define SC_SMEM_BYTES (SC_HEND*2 + 256*4)    /* + 256 floats = 71680 B */

__global__ void __launch_bounds__(256, 2) stepC_kernel(
    const __half* __restrict__ phiq16, const __half* __restrict__ phik16,
    const __half* __restrict__ v16, const __half* __restrict__ kvp16,
    __half* __restrict__ oh)
{
    extern __shared__ __half sm16[];
    float* smf = (float*)(sm16 + SC_HEND);
    float* sZ  = smf;
    float* sZ2 = smf + 64;
    float* sSp = smf + 128;

    const int c = blockIdx.x, bh = blockIdx.y;
    const int b = bh >> 4, h = bh & 15;
    const int tid = threadIdx.x, wid = tid >> 5, lane = tid & 31;
    const int wy = wid & 1, wx = wid >> 1;          // 2(M) x 4(N)
    const int n0 = c * CHUNK;
    const uint32_t sb = smem_u32(sm16);

    const int a_rl = lane & 15, a_ko = (lane >> 4) * 8;
    const int b_nl = (lane & 7) + (lane >> 4) * 8, b_ko = ((lane >> 3) & 1) * 8;

    if (tid < 128) { sZ[tid & 63] = 0.f; sZ2[tid & 63] = 0.f; }
    for (int i = tid; i < 1024; i += 256) {
        int r = i >> 4, seg = (i & 15) * 8;
        size_t gq = ((size_t)bh*SEQ + n0 + r)*MFEAT + seg;
        *(uint4*)&sm16[SC_Q + r*136 + seg] = *(const uint4*)&phiq16[gq];
        *(uint4*)&sm16[SC_K + r*136 + seg] = *(const uint4*)&phik16[gq];
    }
    for (int i = tid; i < 4096; i += 256) {
        int d = i & 63, j = i >> 6;
        sm16[SC_VT + d*72 + j] =
            v16[((size_t)(b*SEQ + n0 + j))*EDIM + h*HDIM + d];
    }
    {
        size_t kb = ((size_t)bh * NCHUNK + c) * MFEAT;
        for (int i = tid; i < 8192; i += 256) {
            int d = i & 63, m = i >> 6;
            sm16[SC_KT + d*136 + m] = kvp16[(kb + m)*HDIM + d];
        }
        if (tid < 128) sSp[tid] = d_spre[kb + tid];
    }
    __syncthreads();

    float accA[2][2][4];
#pragma unroll
    for (int i = 0; i < 2; i++)
#pragma unroll
        for (int j = 0; j < 2; j++)
#pragma unroll
            for (int d = 0; d < 4; d++) accA[i][j][d] = 0.f;

    const uint32_t qb = sb + SC_Q*2, kbb = sb + SC_K*2;
#pragma unroll
    for (int ks = 0; ks < 8; ks++) {
        uint32_t ah[2][4];
#pragma unroll
        for (int mi = 0; mi < 2; mi++)
            LDSM4(ah[mi], qb + (wy*32 + mi*16 + a_rl)*272 + (ks*16 + a_ko)*2);
        uint32_t bfr[4];
        LDSM4(bfr, kbb + (wx*16 + b_nl)*272 + (ks*16 + b_ko)*2);
#pragma unroll
        for (int mi = 0; mi < 2; mi++) {
            MMAH16816(accA[mi][0], ah[mi], bfr[0], bfr[1]);
            MMAH16816(accA[mi][1], ah[mi], bfr[2], bfr[3]);
        }
    }

#pragma unroll
    for (int mi = 0; mi < 2; mi++) {
        int r0 = wy*32 + mi*16 + (lane >> 2);
        int r1 = r0 + 8;
        float z0 = 0.f, z1 = 0.f;
#pragma unroll
        for (int ng = 0; ng < 2; ng++) {
            int cc = wx*16 + ng*8 + (lane & 3)*2;
            float a0 = (cc     <= r0) ? accA[mi][ng][0] : 0.f;
            float a1 = (cc + 1 <= r0) ? accA[mi][ng][1] : 0.f;
            float a2 = (cc     <= r1) ? accA[mi][ng][2] : 0.f;
            float a3 = (cc + 1 <= r1) ? accA[mi][ng][3] : 0.f;
            z0 += a0 + a1; z1 += a2 + a3;
            __half2 h01 = __floats2half2_rn(a0, a1);
            __half2 h23 = __floats2half2_rn(a2, a3);
            *(__half2*)&sm16[SC_A + r0*72 + cc] = h01;
            *(__half2*)&sm16[SC_A + r1*72 + cc] = h23;
        }
        z0 += __shfl_xor_sync(0xffffffffu, z0, 1);
        z0 += __shfl_xor_sync(0xffffffffu, z0, 2);
        z1 += __shfl_xor_sync(0xffffffffu, z1, 1);
        z1 += __shfl_xor_sync(0xffffffffu, z1, 2);
        if ((lane & 3) == 0) {
            atomicAdd(&sZ[r0], z0);
            atomicAdd(&sZ[r1], z1);
        }
    }
    __syncthreads();

    float acc[2][2][4];
#pragma unroll
    for (int i = 0; i < 2; i++)
#pragma unroll
        for (int j = 0; j < 2; j++)
#pragma unroll
            for (int d = 0; d < 4; d++) acc[i][j][d] = 0.f;

    const uint32_t ab = sb + SC_A*2, vtb = sb + SC_VT*2, ktb = sb + SC_KT*2;
#pragma unroll
    for (int ks = 0; ks < 4; ks++) {
        uint32_t ah[2][4];
#pragma unroll
        for (int mi = 0; mi < 2; mi++)
            LDSM4(ah[mi], ab + (wy*32 + mi*16 + a_rl)*144 + (ks*16 + a_ko)*2);
        uint32_t bfr[4];
        LDSM4(bfr, vtb + (wx*16 + b_nl)*144 + (ks*16 + b_ko)*2);
#pragma unroll
        for (int mi = 0; mi < 2; mi++) {
            MMAH16816(acc[mi][0], ah[mi], bfr[0], bfr[1]);
            MMAH16816(acc[mi][1], ah[mi], bfr[2], bfr[3]);
        }
    }
#pragma unroll
    for (int ks = 0; ks < 8; ks++) {
        uint32_t ah[2][4];
#pragma unroll
        for (int mi = 0; mi < 2; mi++)
            LDSM4(ah[mi], qb + (wy*32 + mi*16 + a_rl)*272 + (ks*16 + a_ko)*2);
        uint32_t bfr[4];
        LDSM4(bfr, ktb + (wx*16 + b_nl)*272 + (ks*16 + b_ko)*2);
#pragma unroll
        for (int mi = 0; mi < 2; mi++) {
            MMAH16816(acc[mi][0], ah[mi], bfr[0], bfr[1]);
            MMAH16816(acc[mi][1], ah[mi], bfr[2], bfr[3]);
        }
    }

    if (tid < 64) {
        float z = 0.f;
#pragma unroll 8
        for (int mm = 0; mm < 64; mm++) {
            __half2 qq = *(__half2*)&sm16[SC_Q + tid*136 + mm*2];
            float2 qf = __half22float2(qq);
            z = fmaf(qf.x, sSp[mm*2],     z);
            z = fmaf(qf.y, sSp[mm*2 + 1], z);
        }
        sZ2[tid] = z;
    }
    __syncthreads();

#pragma unroll
    for (int mi = 0; mi < 2; mi++) {
        int r0 = wy*32 + mi*16 + (lane >> 2);
        int r1 = r0 + 8;
        float inv0 = 1.f / (sZ[r0] + sZ2[r0] + 1e-6f);
        float inv1 = 1.f / (sZ[r1] + sZ2[r1] + 1e-6f);
#pragma unroll
        for (int ng = 0; ng < 2; ng++) {
            int cc = wx*16 + ng*8 + (lane & 3)*2;
            __half2 h0 = __floats2half2_rn(acc[mi][ng][0]*inv0, acc[mi][ng][1]*inv0);
            __half2 h1 = __floats2half2_rn(acc[mi][ng][2]*inv1, acc[mi][ng][3]*inv1);
            *(__half2*)&oh[((size_t)(b*SEQ + n0 + r0))*EDIM + h*HDIM + cc] = h0;
            *(__half2*)&oh[((size_t)(b*SEQ + n0 + r1))*EDIM + h*HDIM + cc] = h1;
        }
    }
}

// ---------------- host launcher --------------------------------------------
extern "C" void kernel_launch(void* const* d_in, const int* in_sizes, int n_in,
                              void* d_out, int out_size)
{
    const float* x     = (const float*)d_in[0];
    const float* omega = (const float*)d_in[1];
    const float* Wq    = (const float*)d_in[2];
    const float* Wk    = (const float*)d_in[3];
    const float* Wv    = (const float*)d_in[4];
    const float* Wo    = (const float*)d_in[5];
    const float* bo    = (const float*)d_in[6];
    float* out = (float*)d_out;

    float *q, *k, *v, *phik;
    cudaGetSymbolAddress((void**)&q,    d_q);
    cudaGetSymbolAddress((void**)&k,    d_k);
    cudaGetSymbolAddress((void**)&v,    d_v);
    cudaGetSymbolAddress((void**)&phik, d_phik);

    __half *x16, *wq16, *wk16, *wv16, *wo16, *at16, *pq16, *pk16, *kvp16;
    cudaGetSymbolAddress((void**)&x16,   d_x16);
    cudaGetSymbolAddress((void**)&wq16,  d_wq16);
    cudaGetSymbolAddress((void**)&wk16,  d_wk16);
    cudaGetSymbolAddress((void**)&wv16,  d_wv16);
    cudaGetSymbolAddress((void**)&wo16,  d_wo16);
    cudaGetSymbolAddress((void**)&at16,  d_at16);
    cudaGetSymbolAddress((void**)&pq16,  d_phiq16);
    cudaGetSymbolAddress((void**)&pk16,  d_phik16);
    cudaGetSymbolAddress((void**)&kvp16, d_kvp16);

    const int SMEM_MMA = 3 * STGK_BYTES;                        // 110592
    cudaFuncSetAttribute(mma_gemm_h,
                         cudaFuncAttributeMaxDynamicSharedMemorySize, SMEM_MMA);
    cudaFuncSetAttribute(phi2_kernel,
                         cudaFuncAttributeMaxDynamicSharedMemorySize, PHI_SMEM_BYTES);
    cudaFuncSetAttribute(stepC_kernel,
                         cudaFuncAttributeMaxDynamicSharedMemorySize, SC_SMEM_BYTES);

    // launches 1-3 (4th = the QKV GEMM -> ncu capture slot)
    reset_kernel<<<1, 1>>>();
    cvt_x_kernel<<<(BATCH*SEQ*EDIM/4)/256, 256>>>(x, x16);
    cvt_w4_kernel<<<dim3((EDIM*EDIM/4)/256, 4), 256>>>(
        Wq, Wk, Wv, Wo, wq16, wk16, wv16, wo16);

    // launch 4: fused QKV projection (fp16 1-term, K-chunk 64, 3-stage)
    mma_gemm_h<<<dim3(EDIM/128, (BATCH*SEQ)/128, 3), 256, SMEM_MMA>>>(
        x16, wq16, wk16, wv16, q, k, v, nullptr, EDIM, EDIM);

    // phi features (q,k arrive pre-scaled; q -> fp16, k -> raw log fp32)
    phi2_kernel<<<dim3(SEQ/128, BH, 2), 256, PHI_SMEM_BYTES>>>(
        q, k, omega, pq16, phik);

    // chunked causal linear attention
    stepA_kernel<<<dim3(NCHUNK, BH), 256>>>(pk16, x16);
    stepB_kernel<<<dim3(BH, 4), 256>>>(kvp16);
    stepC_kernel<<<dim3(NCHUNK, BH), 256, SC_SMEM_BYTES>>>(
        pq16, pk16, x16, kvp16, at16);

    // output projection + bias (fp16 1-term)
    mma_gemm_h<<<dim3(EDIM/128, (BATCH*SEQ)/128, 1), 256, SMEM_MMA>>>(
        at16, wo16, wo16, wo16, out, out, out, bo, EDIM, EDIM);
}